// round 9
// baseline (speedup 1.0000x reference)
#include <cuda_runtime.h>
#include <cstdint>

// Problem constants (fixed by the reference)
#define E    1024
#define NBLK 6
#define FF   4096
#define CC   1000
#define BB   4096

// ---------------- device scratch (no allocations allowed) ----------------
__device__ float g_M[NBLK * E * 8];   // precomputed Wo@Wv per block (E x 8)
__device__ float g_f[2][E];           // f vector, double-buffered by block parity
__device__ float g_h1[2][E];          // h-after-LN1, double-buffered by block parity
__device__ float g_row[CC];           // classifier row

__device__ __forceinline__ float dot4(float4 a, float4 b) {
    return fmaf(a.x, b.x, fmaf(a.y, b.y, fmaf(a.z, b.z, a.w * b.w)));
}

// Prefetch one 128B line into L2. No destination register -> no scoreboard;
// the kernel may retire with prefetches still in flight (background DRAM->L2).
__device__ __forceinline__ void l2_prefetch(const void* p) {
    asm volatile("prefetch.global.L2 [%0];" :: "l"(p));
}

// LayerNorm stats over E values (one per thread, 1024 threads).
__device__ __forceinline__ void ln_stats(float val, float* red1, float* red2,
                                         float* stats, int lane, int wc) {
    float s1 = val, s2 = val * val;
#pragma unroll
    for (int o = 16; o; o >>= 1) {
        s1 += __shfl_xor_sync(0xffffffffu, s1, o);
        s2 += __shfl_xor_sync(0xffffffffu, s2, o);
    }
    if (lane == 0) { red1[wc] = s1; red2[wc] = s2; }
    __syncthreads();
    if (wc == 0) {
        float a = red1[lane], c = red2[lane];
#pragma unroll
        for (int o = 16; o; o >>= 1) {
            a += __shfl_xor_sync(0xffffffffu, a, o);
            c += __shfl_xor_sync(0xffffffffu, c, o);
        }
        if (lane == 0) {
            float mean = a * (1.0f / E);
            float var  = c * (1.0f / E) - mean * mean;
            stats[0] = mean;
            stats[1] = rsqrtf(fmaxf(var, 0.f) + 1e-5f);
        }
    }
    __syncthreads();
}

// ================= K_M: M_blk = Wo_blk @ Wv_blk  (E x 8 per block) =========
// grid = 192 CTAs x 256 threads: CTA c -> blk = c/32, rows (c%32)*32 .. +32.
// Also issues background L2 prefetch of W2 block 0 (~3 lines/thread).
__global__ void __launch_bounds__(256)
km_kernel(const float* __restrict__ Wo, const float* __restrict__ Wv,
          const float* __restrict__ W2)
{
    __shared__ __align__(16) float wv_s[E * 8];   // 32KB
    const int tid = threadIdx.x, lane = tid & 31, w = tid >> 5;
    const int blk  = blockIdx.x >> 5;
    const int row0 = (blockIdx.x & 31) * 32;

    const float4* wvg = (const float4*)(Wv + (size_t)blk * E * 8);
    float4* wv4 = (float4*)wv_s;
    for (int i = tid; i < E * 8 / 4; i += 256) wv4[i] = wvg[i];
    __syncthreads();

    const int r0 = row0 + 4 * w;
    const float* wo0 = Wo + (size_t)blk * E * E + (size_t)r0 * E;

    float acc[4][8];
#pragma unroll
    for (int r = 0; r < 4; r++)
#pragma unroll
        for (int j = 0; j < 8; j++) acc[r][j] = 0.f;

#pragma unroll
    for (int kk = 0; kk < 8; kk++) {
        int k4 = lane + 32 * kk;
        float4 wo4[4];
#pragma unroll
        for (int r = 0; r < 4; r++)
            wo4[r] = ((const float4*)(wo0 + (size_t)r * E))[k4];
#pragma unroll
        for (int q = 0; q < 4; q++) {
            int k = 4 * k4 + q;
            float4 a = wv4[2 * k], c = wv4[2 * k + 1];
#pragma unroll
            for (int r = 0; r < 4; r++) {
                float s = (q == 0) ? wo4[r].x : (q == 1) ? wo4[r].y
                        : (q == 2) ? wo4[r].z : wo4[r].w;
                acc[r][0] = fmaf(s, a.x, acc[r][0]);
                acc[r][1] = fmaf(s, a.y, acc[r][1]);
                acc[r][2] = fmaf(s, a.z, acc[r][2]);
                acc[r][3] = fmaf(s, a.w, acc[r][3]);
                acc[r][4] = fmaf(s, c.x, acc[r][4]);
                acc[r][5] = fmaf(s, c.y, acc[r][5]);
                acc[r][6] = fmaf(s, c.z, acc[r][6]);
                acc[r][7] = fmaf(s, c.w, acc[r][7]);
            }
        }
    }

    // Background L2 prefetch of W2 block 0:
    // 16MB = 131072 lines; 192*256 = 49152 threads -> <=3 lines each.
    {
        const char* nxt = (const char*)W2;
        const int lines = (E * FF * 4) / 128;          // 131072
        int gt = blockIdx.x * 256 + tid;
        int nthr = gridDim.x * 256;                    // 49152
#pragma unroll
        for (int rep = 0; rep < 3; rep++) {
            int l = gt + rep * nthr;
            if (l < lines) l2_prefetch(nxt + (size_t)l * 128);
        }
    }

#pragma unroll
    for (int r = 0; r < 4; r++) {
#pragma unroll
        for (int j = 0; j < 8; j++) {
#pragma unroll
            for (int o = 16; o; o >>= 1)
                acc[r][j] += __shfl_xor_sync(0xffffffffu, acc[r][j], o);
        }
        if (lane == 0) {
            float4* mrow = (float4*)(g_M + ((size_t)blk * E + r0 + r) * 8);
            mrow[0] = make_float4(acc[r][0], acc[r][1], acc[r][2], acc[r][3]);
            mrow[1] = make_float4(acc[r][4], acc[r][5], acc[r][6], acc[r][7]);
        }
    }
}

// ================= K_F(blk): one transformer block ==========================
// grid = 148 CTAs x 1024. Prologue FIRST (clean L1tex queue), then the dot
// reads W2_blk from L2 (prefetched by the previous node), then issues
// prefetch.global.L2 for W2_{blk+1} (or Wc) - non-blocking background fill.
__global__ void __launch_bounds__(1024)
kf_kernel(int blk,
          const float* __restrict__ W1,   const float* __restrict__ W2,
          const float* __restrict__ Wc,
          const float* __restrict__ phi_q, const float* __restrict__ phi_f,
          const float* __restrict__ ln1_g, const float* __restrict__ ln1_b,
          const float* __restrict__ ln2_g, const float* __restrict__ ln2_b)
{
    __shared__ __align__(16) float r_s[FF];
    __shared__ __align__(16) float h_s[E];
    __shared__ float red1[32], red2[32], stats[2], m_s[8];
    __shared__ float red_dot[7][4];

    const int tid = threadIdx.x, lane = tid & 31, wc = tid >> 5;
    const int b = blockIdx.x;
    const int cur = blk & 1, prev = (blk + 1) & 1;

    // ---- 1) prologue (no bulk loads competing in the L1tex queue) ----
    float hp;
    if (blk == 0) {
        hp = 1.0f + (float)(tid & 1);                    // h0 = [1,2,1,2,...]
    } else {
        float val = g_h1[prev][tid] + g_f[prev][tid];
        ln_stats(val, red1, red2, stats, lane, wc);
        hp = (val - stats[0]) * stats[1] * ln2_g[(blk - 1) * E + tid]
           + ln2_b[(blk - 1) * E + tid];
    }
    h_s[tid] = hp;
    __syncthreads();
    if (tid < 8) m_s[tid] = cosf(h_s[tid] + phi_q[blk * 8 + tid]);
    __syncthreads();
    float attn;
    {
        const float4* mrow = (const float4*)(g_M + ((size_t)blk * E + tid) * 8);
        float4 a = mrow[0], c = mrow[1];
        attn = a.x * m_s[0] + a.y * m_s[1] + a.z * m_s[2] + a.w * m_s[3]
             + c.x * m_s[4] + c.y * m_s[5] + c.z * m_s[6] + c.w * m_s[7];
    }
    float h1;
    {
        float val = hp + attn;
        ln_stats(val, red1, red2, stats, lane, wc);
        h1 = (val - stats[0]) * stats[1] * ln1_g[blk * E + tid]
           + ln1_b[blk * E + tid];
    }
    if (b == 0) g_h1[cur][tid] = h1;                      // for next node
    h_s[tid] = h1;
    __syncthreads();
    if (tid < 4) m_s[tid] = cosf(h_s[tid]) * cosf(phi_f[blk * 4 + tid]);
    __syncthreads();
    {
        const float4* w1 = (const float4*)W1 + (size_t)blk * FF;  // FF rows of float4
        float m0 = m_s[0], m1 = m_s[1], m2 = m_s[2], m3 = m_s[3];
#pragma unroll
        for (int j = 0; j < FF / 1024; j++) {
            int ff = tid + j * 1024;
            float4 w = w1[ff];
            r_s[ff] = fmaxf(w.x * m0 + w.y * m1 + w.z * m2 + w.w * m3, 0.f);
        }
    }
    __syncthreads();

    // ---- 2) dot: W2_blk rows (L2-warm) x r ----
    const int i = wc >> 2;                 // 0..7 row within CTA (7 valid)
    const int p = wc & 3;                  // 0..3 row segment
    const int row = b * 7 + i;
    const bool active = (i < 7) && (row < E);

    float4 wreg[8];
    if (active) {
        const float4* src = (const float4*)W2 + (size_t)blk * E * (FF / 4)
                          + (size_t)row * (FF / 4) + p * 256 + lane;
#pragma unroll
        for (int j = 0; j < 8; j++) wreg[j] = src[32 * j];   // issue (L2 hits)
    }

    // ---- 3) background L2 prefetch of the NEXT big operand ----
    {
        const char* nxt;
        int lines;
        if (blk < NBLK - 1) { nxt = (const char*)(W2 + (size_t)(blk + 1) * E * FF);
                              lines = (E * FF * 4) / 128; }          // 131072
        else               { nxt = (const char*)Wc;
                              lines = (CC * E * 4) / 128; }          // 32000
        int gt = b * 1024 + tid;            // 151552 threads >= lines
        if (gt < lines) l2_prefetch(nxt + (size_t)gt * 128);
    }

    if (active) {
        const float4* r4 = (const float4*)r_s;
        float acc = 0.f;
#pragma unroll
        for (int j = 0; j < 8; j++)
            acc += dot4(wreg[j], r4[p * 256 + lane + 32 * j]);
#pragma unroll
        for (int o = 16; o; o >>= 1) acc += __shfl_xor_sync(0xffffffffu, acc, o);
        if (lane == 0) red_dot[i][p] = acc;
    }
    __syncthreads();
    if (tid < 7 && b * 7 + tid < E) {
        float s = red_dot[tid][0] + red_dot[tid][1] + red_dot[tid][2] + red_dot[tid][3];
        g_f[cur][b * 7 + tid] = s;
    }
}

// ================= K_CLS: LN2-final + classifier (Wc L2-warm) ==============
// grid = 125 CTAs x 1024. CTA b owns Wc rows [8b, 8b+8).
__global__ void __launch_bounds__(1024)
kcls_kernel(const float* __restrict__ Wc, const float* __restrict__ bc,
            const float* __restrict__ ln2_g, const float* __restrict__ ln2_b)
{
    __shared__ __align__(16) float h_s[E];
    __shared__ float red1[32], red2[32], stats[2];
    __shared__ float red_cls[8][4];

    const int tid = threadIdx.x, lane = tid & 31, wc = tid >> 5;
    const int b = blockIdx.x;
    const int r = wc >> 2, p = wc & 3;         // 8 rows x 4 warp-parts

    // h_final = LN2 of block 5 (parity: 5&1 = 1)
    {
        float val = g_h1[1][tid] + g_f[1][tid];
        ln_stats(val, red1, red2, stats, lane, wc);
        h_s[tid] = (val - stats[0]) * stats[1] * ln2_g[5 * E + tid]
                 + ln2_b[5 * E + tid];
    }
    __syncthreads();

    const float4* src = (const float4*)Wc + ((size_t)b * 8 + r) * 256;
    float4 w0 = src[p * 64 + lane];
    float4 w1 = src[p * 64 + lane + 32];

    const float4* h4 = (const float4*)h_s;
    float acc = dot4(w0, h4[p * 64 + lane]) + dot4(w1, h4[p * 64 + lane + 32]);
#pragma unroll
    for (int o = 16; o; o >>= 1) acc += __shfl_xor_sync(0xffffffffu, acc, o);
    if (lane == 0) red_cls[r][p] = acc;
    __syncthreads();
    if (tid < 8) {
        float s = red_cls[tid][0] + red_cls[tid][1] + red_cls[tid][2] + red_cls[tid][3];
        g_row[b * 8 + tid] = s + bc[b * 8 + tid];
    }
}

// ================= K_BCAST: broadcast row to all B output rows =============
__global__ void __launch_bounds__(1024)
kb_kernel(float* __restrict__ out)
{
    __shared__ __align__(16) float row_s[CC];
    const int tid = threadIdx.x, lane = tid & 31;
    if (tid < CC) row_s[tid] = g_row[tid];
    __syncthreads();

    const int gwarp = blockIdx.x * 32 + (tid >> 5);
    const int nwarps = gridDim.x * 32;
    const float4* r4 = (const float4*)row_s;               // 250 float4
    for (int r = gwarp; r < BB; r += nwarps) {
        float4* dst = (float4*)out + (size_t)r * (CC / 4);
        for (int j = lane; j < CC / 4; j += 32) dst[j] = r4[j];
    }
}

// ================= host launch =============================================
extern "C" void kernel_launch(void* const* d_in, const int* in_sizes, int n_in,
                              void* d_out, int out_size) {
    // metadata order: 0:x 1:Wq 2:Wk 3:Wv 4:Wo 5:phi_q 6:W1 7:W2 8:phi_f
    //                 9:ln1_g 10:ln1_b 11:ln2_g 12:ln2_b 13:Wc 14:bc
    const float* Wv    = (const float*)d_in[3];
    const float* Wo    = (const float*)d_in[4];
    const float* phi_q = (const float*)d_in[5];
    const float* W1    = (const float*)d_in[6];
    const float* W2    = (const float*)d_in[7];
    const float* phi_f = (const float*)d_in[8];
    const float* ln1_g = (const float*)d_in[9];
    const float* ln1_b = (const float*)d_in[10];
    const float* ln2_g = (const float*)d_in[11];
    const float* ln2_b = (const float*)d_in[12];
    const float* Wc    = (const float*)d_in[13];
    const float* bc    = (const float*)d_in[14];

    km_kernel<<<192, 256>>>(Wo, Wv, W2);
    for (int blk = 0; blk < NBLK; blk++)
        kf_kernel<<<148, 1024>>>(blk, W1, W2, Wc, phi_q, phi_f,
                                 ln1_g, ln1_b, ln2_g, ln2_b);
    kcls_kernel<<<125, 1024>>>(Wc, bc, ln2_g, ln2_b);
    kb_kernel<<<148, 1024>>>((float*)d_out);
}